// round 13
// baseline (speedup 1.0000x reference)
#include <cuda_runtime.h>
#include <cuda_fp16.h>
#include <cstdint>

#define T_TOK 16384
#define DIM   1024
#define NE    8
#define FDIM  4096

#define TM 128
#define TN 128
#define TK 64
#define LDA 72          // padded fp16 K-stride in smem (conflict-free ldmatrix)
#define MAT_BYTES (128 * LDA * 2)      // 18432
#define STAGE_BYTES (2 * MAT_BYTES)    // Ah, Bh = 36864
#define NSTAGE 3
#define SMEM_SZ (NSTAGE * STAGE_BYTES) // 110592 -> 2 CTAs/SM

// ---------------- device scratch (referenced ONLY from device code) ----------------
__device__ int   g_idx[T_TOK];
__device__ int   g_counts[NE];
__device__ int   g_offsets[NE + 1];
__device__ int   g_cursor[NE];
__device__ int   g_perm[T_TOK];

__device__ __half g_xs[(size_t)T_TOK * DIM];        // gathered x, fp16
__device__ __half g_w1_h[(size_t)NE * FDIM * DIM];  // [e][n=F][k=D]
__device__ __half g_w2_h[(size_t)NE * DIM * FDIM];  // [e][n=D][k=F]
__device__ __half g_h[(size_t)T_TOK * FDIM];        // hidden, fp16

// ---------------- helpers ----------------
__device__ __forceinline__ uint32_t smem_u32(const void* p) {
    uint32_t a;
    asm("{ .reg .u64 t; cvta.to.shared.u64 t, %1; cvt.u32.u64 %0, t; }"
        : "=r"(a) : "l"(p));
    return a;
}

__device__ __forceinline__ void ldm_x4(uint32_t* r, uint32_t addr) {
    asm volatile("ldmatrix.sync.aligned.m8n8.x4.shared.b16 {%0,%1,%2,%3}, [%4];"
                 : "=r"(r[0]), "=r"(r[1]), "=r"(r[2]), "=r"(r[3]) : "r"(addr));
}
__device__ __forceinline__ void mma_f16_2(float* c, const uint32_t* a,
                                          uint32_t b0, uint32_t b1) {
    asm volatile(
        "mma.sync.aligned.m16n8k16.row.col.f32.f16.f16.f32 "
        "{%0,%1,%2,%3}, {%4,%5,%6,%7}, {%8,%9}, {%0,%1,%2,%3};"
        : "+f"(c[0]), "+f"(c[1]), "+f"(c[2]), "+f"(c[3])
        : "r"(a[0]), "r"(a[1]), "r"(a[2]), "r"(a[3]), "r"(b0), "r"(b1));
}
__device__ __forceinline__ void cp16(uint32_t sa, const void* g) {
    uint64_t ga = __cvta_generic_to_global(g);
    asm volatile("cp.async.cg.shared.global [%0], [%1], 16;" :: "r"(sa), "l"(ga));
}

// ---------------- router / prefix / scatter ----------------
__global__ void init_kernel() {
    int t = threadIdx.x;
    if (t < NE) { g_counts[t] = 0; g_cursor[t] = 0; }
}

__global__ __launch_bounds__(256) void router_kernel(
    const float* __restrict__ x, const float* __restrict__ rw,
    const float* __restrict__ rb)
{
    int t = blockIdx.x;
    int w = threadIdx.x >> 5;
    int l = threadIdx.x & 31;
    const float* xr = x + (size_t)t * DIM;
    float s = 0.f;
    for (int d = l; d < DIM; d += 32)
        s += xr[d] * rw[d * NE + w];
    #pragma unroll
    for (int o = 16; o; o >>= 1)
        s += __shfl_down_sync(0xffffffffu, s, o);
    __shared__ float lg[NE];
    if (l == 0) lg[w] = s + rb[w];
    __syncthreads();
    if (threadIdx.x == 0) {
        int best = 0; float bv = lg[0];
        #pragma unroll
        for (int e = 1; e < NE; e++)
            if (lg[e] > bv) { bv = lg[e]; best = e; }
        g_idx[t] = best;
        atomicAdd(&g_counts[best], 1);
    }
}

__global__ void prefix_kernel(float* __restrict__ out, int out_size) {
    if (threadIdx.x == 0) {
        int acc = 0; float lb = 0.f;
        for (int e = 0; e < NE; e++) {
            g_offsets[e] = acc;
            acc += g_counts[e];
            float u = (float)g_counts[e] / (float)T_TOK - 1.0f / (float)NE;
            lb += u * u;
        }
        g_offsets[NE] = acc;
        lb /= (float)NE;
        if (out_size > T_TOK * DIM)
            out[(size_t)T_TOK * DIM] = lb;
    }
}

__global__ void scatter_kernel() {
    int t = blockIdx.x * blockDim.x + threadIdx.x;
    if (t < T_TOK) {
        int e = g_idx[t];
        int p = atomicAdd(&g_cursor[e], 1);
        g_perm[g_offsets[e] + p] = t;
    }
}

// ---------------- conversions ----------------
__global__ void cvt_x_kernel(const float* __restrict__ x) {
    size_t i = ((size_t)blockIdx.x * blockDim.x + threadIdx.x) * 4;
    if (i >= (size_t)T_TOK * DIM) return;
    int r = (int)(i / DIM), d = (int)(i % DIM);
    const float4 v = *(const float4*)(x + (size_t)g_perm[r] * DIM + d);
    __half2 t0; t0.x = __float2half(v.x); t0.y = __float2half(v.y);
    __half2 t1; t1.x = __float2half(v.z); t1.y = __float2half(v.w);
    *(__half2*)(g_xs + i)     = t0;
    *(__half2*)(g_xs + i + 2) = t1;
}

// transpose + round to fp16: src [SR, SC] per expert -> dst [SC, SR]
// 32(c) x 64(r) tiles; half2 coalesced stores.
template<int SR, int SC, bool W1>
__global__ __launch_bounds__(256) void tsplit_kernel(const float* __restrict__ w)
{
    __shared__ float tile[32][65];   // [c][r], pad -> conflict-free
    int e = blockIdx.z;
    int c0 = blockIdx.x * 32;
    int r0 = blockIdx.y * 64;
    const float* src = w + (size_t)e * SR * SC;
    int tx = threadIdx.x, ty = threadIdx.y;   // (32, 8)
    #pragma unroll
    for (int j = 0; j < 64; j += 8)
        tile[tx][ty + j] = src[(size_t)(r0 + ty + j) * SC + (c0 + tx)];
    __syncthreads();
    __half* oh = (W1 ? g_w1_h : g_w2_h) + (size_t)e * SR * SC;
    #pragma unroll
    for (int j = 0; j < 32; j += 8) {
        int c = ty + j;
        __half2 v;
        v.x = __float2half(tile[c][2 * tx]);
        v.y = __float2half(tile[c][2 * tx + 1]);
        *(__half2*)(oh + (size_t)(c0 + c) * SR + r0 + 2 * tx) = v;
    }
}

// ---------------- grouped fp16 mma.sync GEMM (single-pass) ----------------
// CTA 128x128, warp 64x32 (8 warps 2x4), TK=64, register double-buffered frags.
template<int KTOT, bool G1>
__global__ __launch_bounds__(256, 2) void moe_mma_kernel(
    const float* __restrict__ bias, float* __restrict__ Of)
{
    constexpr int NTOT = G1 ? FDIM : DIM;
    constexpr int NCH  = KTOT / TK;

    const __half* __restrict__ Ah = G1 ? g_xs : g_h;
    const __half* __restrict__ Bh = G1 ? g_w1_h : g_w2_h;

    int e = blockIdx.z;
    int seg0 = g_offsets[e], seg1 = g_offsets[e + 1];
    int m0 = seg0 + blockIdx.y * TM;
    if (m0 >= seg1) return;
    int mcnt = min(TM, seg1 - m0);
    int n0 = blockIdx.x * TN;

    extern __shared__ char smem[];
    uint32_t sbase = smem_u32(smem);

    int tid = threadIdx.x;
    int wid = tid >> 5, lane = tid & 31;
    int warp_m = (wid >> 2) * 64;   // 0 or 64
    int warp_n = (wid & 3) * 32;    // 0,32,64,96

    const __half* Beh = Bh + (size_t)e * NTOT * KTOT;
    const float* be = bias + (size_t)e * NTOT;

    auto prefetch = [&](int it) {
        if (it < NCH) {
            int k0 = it * TK;
            uint32_t stg = sbase + (uint32_t)(it % NSTAGE) * STAGE_BYTES;
            #pragma unroll
            for (int i = 0; i < 8; i++) {
                int c   = i * 256 + tid;          // 0..2047
                int mat = c >> 10;                // 0:Ah 1:Bh
                int rw  = (c & 1023) >> 3;        // 0..127
                int sg  = c & 7;                  // 16B segment in 128B row
                uint32_t sa = stg + mat * MAT_BYTES + (rw * LDA + sg * 8) * 2;
                const __half* gp;
                if (mat == 0) {
                    int gr = m0 + rw;
                    if (gr > T_TOK - 1) gr = T_TOK - 1;   // clamp; never stored
                    gp = Ah + (size_t)gr * KTOT + k0 + sg * 8;
                } else {
                    gp = Beh + (size_t)(n0 + rw) * KTOT + k0 + sg * 8;
                }
                cp16(sa, gp);
            }
        }
        asm volatile("cp.async.commit_group;" ::: "memory");
    };

    float acc[4][4][4];
    #pragma unroll
    for (int i = 0; i < 4; i++)
        #pragma unroll
        for (int j = 0; j < 4; j++)
            #pragma unroll
            for (int q = 0; q < 4; q++) acc[i][j][q] = 0.f;

    prefetch(0);
    prefetch(1);

    // fragment addresses
    int acolo = (lane >> 4) << 3;       // 0 or 8
    int arow  = lane & 15;
    int bg    = lane >> 3;
    int brow  = ((bg >> 1) << 3) + (lane & 7);
    int bcolo = (bg & 1) << 3;

    uint32_t afh[2][4][4], bfh[2][2][4];

    for (int it = 0; it < NCH; ++it) {
        asm volatile("cp.async.wait_group 1;" ::: "memory");
        __syncthreads();        // stage `it` visible; stage (it-1) reads all done

        uint32_t stg = sbase + (uint32_t)(it % NSTAGE) * STAGE_BYTES;
        uint32_t sAh = stg;
        uint32_t sBh = stg + MAT_BYTES;

        // preload kst=0 fragments into buffer 0
        {
            int acol = acolo, bcol = bcolo;
            #pragma unroll
            for (int mt = 0; mt < 4; ++mt)
                ldm_x4(afh[0][mt], sAh + (uint32_t)((warp_m + mt * 16 + arow) * LDA + acol) * 2);
            #pragma unroll
            for (int p = 0; p < 2; ++p)
                ldm_x4(bfh[0][p], sBh + (uint32_t)((warp_n + p * 16 + brow) * LDA + bcol) * 2);
        }

        #pragma unroll
        for (int kst = 0; kst < 4; ++kst) {
            int cur = kst & 1, nxt = cur ^ 1;
            if (kst < 3) {      // load kst+1 fragments while kst mma run
                int acol = (kst + 1) * 16 + acolo;
                int bcol = (kst + 1) * 16 + bcolo;
                #pragma unroll
                for (int mt = 0; mt < 4; ++mt)
                    ldm_x4(afh[nxt][mt], sAh + (uint32_t)((warp_m + mt * 16 + arow) * LDA + acol) * 2);
                #pragma unroll
                for (int p = 0; p < 2; ++p)
                    ldm_x4(bfh[nxt][p], sBh + (uint32_t)((warp_n + p * 16 + brow) * LDA + bcol) * 2);
            }
            if (kst == 0)
                prefetch(it + 2);   // cp.async after next-buffer ldmatrix issues
            #pragma unroll
            for (int mt = 0; mt < 4; ++mt)
                #pragma unroll
                for (int p = 0; p < 2; ++p) {
                    mma_f16_2(acc[mt][2 * p],     afh[cur][mt], bfh[cur][p][0], bfh[cur][p][1]);
                    mma_f16_2(acc[mt][2 * p + 1], afh[cur][mt], bfh[cur][p][2], bfh[cur][p][3]);
                }
        }
    }

    // ---- epilogue ----
    int rbase = warp_m + (lane >> 2);
    int cbase = n0 + warp_n + (lane & 3) * 2;
    #pragma unroll
    for (int nt = 0; nt < 4; ++nt) {
        int gc = cbase + nt * 8;
        float b0 = be[gc], b1 = be[gc + 1];
        #pragma unroll
        for (int mt = 0; mt < 4; ++mt) {
            #pragma unroll
            for (int s = 0; s < 2; ++s) {
                int lr = rbase + mt * 16 + s * 8;
                if (lr < mcnt) {
                    int gr = m0 + lr;
                    float f0 = acc[mt][nt][2 * s]     + b0;
                    float f1 = acc[mt][nt][2 * s + 1] + b1;
                    if constexpr (G1) {
                        f0 = fmaxf(f0, 0.f);
                        f1 = fmaxf(f1, 0.f);
                        __half2 th;
                        th.x = __float2half(f0);
                        th.y = __float2half(f1);
                        *(__half2*)(g_h + (size_t)gr * FDIM + gc) = th;
                    } else {
                        int orow = g_perm[gr];
                        float2 v; v.x = f0; v.y = f1;
                        *(float2*)(Of + (size_t)orow * DIM + gc) = v;
                    }
                }
            }
        }
    }
}

// ---------------- launch ----------------
extern "C" void kernel_launch(void* const* d_in, const int* in_sizes, int n_in,
                              void* d_out, int out_size)
{
    const float* x  = (const float*)d_in[0];
    const float* rw = (const float*)d_in[1];
    const float* rb = (const float*)d_in[2];
    const float* w1 = (const float*)d_in[3];
    const float* b1 = (const float*)d_in[4];
    const float* w2 = (const float*)d_in[5];
    const float* b2 = (const float*)d_in[6];
    float* out = (float*)d_out;

    cudaFuncSetAttribute(moe_mma_kernel<DIM, true>,
                         cudaFuncAttributeMaxDynamicSharedMemorySize, SMEM_SZ);
    cudaFuncSetAttribute(moe_mma_kernel<FDIM, false>,
                         cudaFuncAttributeMaxDynamicSharedMemorySize, SMEM_SZ);

    init_kernel<<<1, 32>>>();
    router_kernel<<<T_TOK, 256>>>(x, rw, rb);
    prefix_kernel<<<1, 32>>>(out, out_size);
    scatter_kernel<<<(T_TOK + 255) / 256, 256>>>();

    cvt_x_kernel<<<(T_TOK * DIM / 4 + 255) / 256, 256>>>(x);
    tsplit_kernel<DIM, FDIM, true><<<dim3(FDIM / 32, DIM / 64, NE), dim3(32, 8)>>>(w1);
    tsplit_kernel<FDIM, DIM, false><<<dim3(DIM / 32, FDIM / 64, NE), dim3(32, 8)>>>(w2);

    moe_mma_kernel<DIM, true><<<dim3(FDIM / TN, T_TOK / TM, NE), 256, SMEM_SZ>>>(b1, nullptr);
    moe_mma_kernel<FDIM, false><<<dim3(DIM / TN, T_TOK / TM, NE), 256, SMEM_SZ>>>(b2, out);
}

// round 14
// speedup vs baseline: 1.0505x; 1.0505x over previous
#include <cuda_runtime.h>
#include <cuda_fp16.h>
#include <cstdint>

#define T_TOK 16384
#define DIM   1024
#define NE    8
#define FDIM  4096

#define TM 128
#define TN 128
#define TK 64
#define LDA 72          // padded fp16 K-stride in smem (conflict-free ldmatrix)
#define MAT_BYTES (128 * LDA * 2)      // 18432
#define STAGE_BYTES (2 * MAT_BYTES)    // Ah, Bh = 36864
#define NSTAGE 3
#define SMEM_SZ (NSTAGE * STAGE_BYTES) // 110592 -> 2 CTAs/SM

// ---------------- device scratch (referenced ONLY from device code) ----------------
__device__ int   g_idx[T_TOK];
__device__ int   g_counts[NE];
__device__ int   g_offsets[NE + 1];
__device__ int   g_cursor[NE];
__device__ int   g_perm[T_TOK];

__device__ __half g_xs[(size_t)T_TOK * DIM];        // gathered x, fp16
__device__ __half g_w1_h[(size_t)NE * FDIM * DIM];  // [e][n=F][k=D]
__device__ __half g_w2_h[(size_t)NE * DIM * FDIM];  // [e][n=D][k=F]
__device__ __half g_h[(size_t)T_TOK * FDIM];        // hidden, fp16

// ---------------- helpers ----------------
__device__ __forceinline__ uint32_t smem_u32(const void* p) {
    uint32_t a;
    asm("{ .reg .u64 t; cvta.to.shared.u64 t, %1; cvt.u32.u64 %0, t; }"
        : "=r"(a) : "l"(p));
    return a;
}

__device__ __forceinline__ void ldm_x4(uint32_t* r, uint32_t addr) {
    asm volatile("ldmatrix.sync.aligned.m8n8.x4.shared.b16 {%0,%1,%2,%3}, [%4];"
                 : "=r"(r[0]), "=r"(r[1]), "=r"(r[2]), "=r"(r[3]) : "r"(addr));
}
__device__ __forceinline__ void mma_f16_2(float* c, const uint32_t* a,
                                          uint32_t b0, uint32_t b1) {
    asm volatile(
        "mma.sync.aligned.m16n8k16.row.col.f32.f16.f16.f32 "
        "{%0,%1,%2,%3}, {%4,%5,%6,%7}, {%8,%9}, {%0,%1,%2,%3};"
        : "+f"(c[0]), "+f"(c[1]), "+f"(c[2]), "+f"(c[3])
        : "r"(a[0]), "r"(a[1]), "r"(a[2]), "r"(a[3]), "r"(b0), "r"(b1));
}
__device__ __forceinline__ void cp16(uint32_t sa, const void* g) {
    uint64_t ga = __cvta_generic_to_global(g);
    asm volatile("cp.async.cg.shared.global [%0], [%1], 16;" :: "r"(sa), "l"(ga));
}

// ---------------- router / prefix / scatter ----------------
__global__ void init_kernel() {
    int t = threadIdx.x;
    if (t < NE) { g_counts[t] = 0; g_cursor[t] = 0; }
}

__global__ __launch_bounds__(256) void router_kernel(
    const float* __restrict__ x, const float* __restrict__ rw,
    const float* __restrict__ rb)
{
    int t = blockIdx.x;
    int w = threadIdx.x >> 5;
    int l = threadIdx.x & 31;
    const float* xr = x + (size_t)t * DIM;
    float s = 0.f;
    for (int d = l; d < DIM; d += 32)
        s += xr[d] * rw[d * NE + w];
    #pragma unroll
    for (int o = 16; o; o >>= 1)
        s += __shfl_down_sync(0xffffffffu, s, o);
    __shared__ float lg[NE];
    if (l == 0) lg[w] = s + rb[w];
    __syncthreads();
    if (threadIdx.x == 0) {
        int best = 0; float bv = lg[0];
        #pragma unroll
        for (int e = 1; e < NE; e++)
            if (lg[e] > bv) { bv = lg[e]; best = e; }
        g_idx[t] = best;
        atomicAdd(&g_counts[best], 1);
    }
}

__global__ void prefix_kernel(float* __restrict__ out, int out_size) {
    if (threadIdx.x == 0) {
        int acc = 0; float lb = 0.f;
        for (int e = 0; e < NE; e++) {
            g_offsets[e] = acc;
            acc += g_counts[e];
            float u = (float)g_counts[e] / (float)T_TOK - 1.0f / (float)NE;
            lb += u * u;
        }
        g_offsets[NE] = acc;
        lb /= (float)NE;
        if (out_size > T_TOK * DIM)
            out[(size_t)T_TOK * DIM] = lb;
    }
}

__global__ void scatter_kernel() {
    int t = blockIdx.x * blockDim.x + threadIdx.x;
    if (t < T_TOK) {
        int e = g_idx[t];
        int p = atomicAdd(&g_cursor[e], 1);
        g_perm[g_offsets[e] + p] = t;
    }
}

// ---------------- conversions ----------------
__global__ void cvt_x_kernel(const float* __restrict__ x) {
    size_t i = ((size_t)blockIdx.x * blockDim.x + threadIdx.x) * 4;
    if (i >= (size_t)T_TOK * DIM) return;
    int r = (int)(i / DIM), d = (int)(i % DIM);
    const float4 v = *(const float4*)(x + (size_t)g_perm[r] * DIM + d);
    __half2 t0; t0.x = __float2half(v.x); t0.y = __float2half(v.y);
    __half2 t1; t1.x = __float2half(v.z); t1.y = __float2half(v.w);
    *(__half2*)(g_xs + i)     = t0;
    *(__half2*)(g_xs + i + 2) = t1;
}

// transpose + round to fp16: src [SR, SC] per expert -> dst [SC, SR]
// 32(c) x 64(r) tiles; half2 coalesced stores.
template<int SR, int SC, bool W1>
__global__ __launch_bounds__(256) void tsplit_kernel(const float* __restrict__ w)
{
    __shared__ float tile[32][65];   // [c][r], pad -> conflict-free
    int e = blockIdx.z;
    int c0 = blockIdx.x * 32;
    int r0 = blockIdx.y * 64;
    const float* src = w + (size_t)e * SR * SC;
    int tx = threadIdx.x, ty = threadIdx.y;   // (32, 8)
    #pragma unroll
    for (int j = 0; j < 64; j += 8)
        tile[tx][ty + j] = src[(size_t)(r0 + ty + j) * SC + (c0 + tx)];
    __syncthreads();
    __half* oh = (W1 ? g_w1_h : g_w2_h) + (size_t)e * SR * SC;
    #pragma unroll
    for (int j = 0; j < 32; j += 8) {
        int c = ty + j;
        __half2 v;
        v.x = __float2half(tile[c][2 * tx]);
        v.y = __float2half(tile[c][2 * tx + 1]);
        *(__half2*)(oh + (size_t)(c0 + c) * SR + r0 + 2 * tx) = v;
    }
}

// ---------------- grouped fp16 mma.sync GEMM (single-pass) ----------------
// CTA 128x128, warp 64x32 (8 warps 2x4), TK=64. C = A[128,K] * B[128,K]^T
template<int KTOT, bool G1>
__global__ __launch_bounds__(256, 2) void moe_mma_kernel(
    const float* __restrict__ bias, float* __restrict__ Of)
{
    constexpr int NTOT = G1 ? FDIM : DIM;
    constexpr int NCH  = KTOT / TK;

    const __half* __restrict__ Ah = G1 ? g_xs : g_h;
    const __half* __restrict__ Bh = G1 ? g_w1_h : g_w2_h;

    int e = blockIdx.z;
    int seg0 = g_offsets[e], seg1 = g_offsets[e + 1];
    int m0 = seg0 + blockIdx.y * TM;
    if (m0 >= seg1) return;
    int mcnt = min(TM, seg1 - m0);
    int n0 = blockIdx.x * TN;

    extern __shared__ char smem[];
    uint32_t sbase = smem_u32(smem);

    int tid = threadIdx.x;
    int wid = tid >> 5, lane = tid & 31;
    int warp_m = (wid >> 2) * 64;   // 0 or 64
    int warp_n = (wid & 3) * 32;    // 0,32,64,96

    const __half* Beh = Bh + (size_t)e * NTOT * KTOT;
    const float* be = bias + (size_t)e * NTOT;

    auto prefetch = [&](int it) {
        if (it < NCH) {
            int k0 = it * TK;
            uint32_t stg = sbase + (uint32_t)(it % NSTAGE) * STAGE_BYTES;
            #pragma unroll
            for (int i = 0; i < 8; i++) {
                int c   = i * 256 + tid;          // 0..2047
                int mat = c >> 10;                // 0:Ah 1:Bh
                int rw  = (c & 1023) >> 3;        // 0..127
                int sg  = c & 7;                  // 16B segment in 128B row
                uint32_t sa = stg + mat * MAT_BYTES + (rw * LDA + sg * 8) * 2;
                const __half* gp;
                if (mat == 0) {
                    int gr = m0 + rw;
                    if (gr > T_TOK - 1) gr = T_TOK - 1;   // clamp; never stored
                    gp = Ah + (size_t)gr * KTOT + k0 + sg * 8;
                } else {
                    gp = Beh + (size_t)(n0 + rw) * KTOT + k0 + sg * 8;
                }
                cp16(sa, gp);
            }
        }
        asm volatile("cp.async.commit_group;" ::: "memory");
    };

    float acc[4][4][4];
    #pragma unroll
    for (int i = 0; i < 4; i++)
        #pragma unroll
        for (int j = 0; j < 4; j++)
            #pragma unroll
            for (int q = 0; q < 4; q++) acc[i][j][q] = 0.f;

    prefetch(0);
    prefetch(1);

    // B x4 address precompute: group g = lane>>3, lr = lane&7
    // row = warp_n + pair*16 + (g>>1)*8 + lr ; col = kst*16 + (g&1)*8
    int bg   = lane >> 3;
    int brow = ((bg >> 1) << 3) + (lane & 7);
    int bcolo = (bg & 1) << 3;

    for (int it = 0; it < NCH; ++it) {
        asm volatile("cp.async.wait_group 1;" ::: "memory");
        __syncthreads();        // stage `it` visible; stage (it-1) reads all done

        uint32_t stg = sbase + (uint32_t)(it % NSTAGE) * STAGE_BYTES;
        uint32_t sAh = stg;
        uint32_t sBh = stg + MAT_BYTES;

        #pragma unroll
        for (int kst = 0; kst < 4; ++kst) {
            uint32_t afh[4][4], bfh[2][4];
            int acol = kst * 16 + ((lane >> 4) << 3);
            int arow_off = (lane & 15);
            #pragma unroll
            for (int mt = 0; mt < 4; ++mt) {
                int row = warp_m + mt * 16 + arow_off;
                ldm_x4(afh[mt], sAh + (uint32_t)(row * LDA + acol) * 2);
            }
            int bcol = kst * 16 + bcolo;
            #pragma unroll
            for (int p = 0; p < 2; ++p) {
                int row = warp_n + p * 16 + brow;
                ldm_x4(bfh[p], sBh + (uint32_t)(row * LDA + bcol) * 2);
            }
            if (kst == 0)
                prefetch(it + 2);   // after critical ldmatrix issues; overwrites (it-1)%3
            // frag(nt=2p)   = {bfh[p][0], bfh[p][1]}  (n rows p*16+0..7)
            // frag(nt=2p+1) = {bfh[p][2], bfh[p][3]}  (n rows p*16+8..15)
            #pragma unroll
            for (int mt = 0; mt < 4; ++mt)
                #pragma unroll
                for (int p = 0; p < 2; ++p) {
                    mma_f16_2(acc[mt][2 * p],     afh[mt], bfh[p][0], bfh[p][1]);
                    mma_f16_2(acc[mt][2 * p + 1], afh[mt], bfh[p][2], bfh[p][3]);
                }
        }
    }

    // ---- epilogue ----
    int rbase = warp_m + (lane >> 2);
    int cbase = n0 + warp_n + (lane & 3) * 2;
    #pragma unroll
    for (int nt = 0; nt < 4; ++nt) {
        int gc = cbase + nt * 8;
        float b0 = be[gc], b1 = be[gc + 1];
        #pragma unroll
        for (int mt = 0; mt < 4; ++mt) {
            #pragma unroll
            for (int s = 0; s < 2; ++s) {
                int lr = rbase + mt * 16 + s * 8;
                if (lr < mcnt) {
                    int gr = m0 + lr;
                    float f0 = acc[mt][nt][2 * s]     + b0;
                    float f1 = acc[mt][nt][2 * s + 1] + b1;
                    if constexpr (G1) {
                        f0 = fmaxf(f0, 0.f);
                        f1 = fmaxf(f1, 0.f);
                        __half2 th;
                        th.x = __float2half(f0);
                        th.y = __float2half(f1);
                        *(__half2*)(g_h + (size_t)gr * FDIM + gc) = th;
                    } else {
                        int orow = g_perm[gr];
                        float2 v; v.x = f0; v.y = f1;
                        *(float2*)(Of + (size_t)orow * DIM + gc) = v;
                    }
                }
            }
        }
    }
}

// ---------------- static side-stream resources (host-side; no device memory) ----
static cudaStream_t g_side_stream;
static cudaEvent_t  g_ev_fork, g_ev_join;
static struct SideInit {
    SideInit() {
        cudaStreamCreateWithFlags(&g_side_stream, cudaStreamNonBlocking);
        cudaEventCreateWithFlags(&g_ev_fork, cudaEventDisableTiming);
        cudaEventCreateWithFlags(&g_ev_join, cudaEventDisableTiming);
    }
} g_side_init;

// ---------------- launch ----------------
extern "C" void kernel_launch(void* const* d_in, const int* in_sizes, int n_in,
                              void* d_out, int out_size)
{
    const float* x  = (const float*)d_in[0];
    const float* rw = (const float*)d_in[1];
    const float* rb = (const float*)d_in[2];
    const float* w1 = (const float*)d_in[3];
    const float* b1 = (const float*)d_in[4];
    const float* w2 = (const float*)d_in[5];
    const float* b2 = (const float*)d_in[6];
    float* out = (float*)d_out;

    cudaFuncSetAttribute(moe_mma_kernel<DIM, true>,
                         cudaFuncAttributeMaxDynamicSharedMemorySize, SMEM_SZ);
    cudaFuncSetAttribute(moe_mma_kernel<FDIM, false>,
                         cudaFuncAttributeMaxDynamicSharedMemorySize, SMEM_SZ);

    // fork: tsplit (depends only on w1/w2) runs on side stream concurrently
    // with the router -> prefix -> scatter -> cvt_x chain on the main stream.
    cudaEventRecord(g_ev_fork, 0);
    cudaStreamWaitEvent(g_side_stream, g_ev_fork, 0);

    tsplit_kernel<DIM, FDIM, true>
        <<<dim3(FDIM / 32, DIM / 64, NE), dim3(32, 8), 0, g_side_stream>>>(w1);
    tsplit_kernel<FDIM, DIM, false>
        <<<dim3(DIM / 32, FDIM / 64, NE), dim3(32, 8), 0, g_side_stream>>>(w2);
    cudaEventRecord(g_ev_join, g_side_stream);

    init_kernel<<<1, 32>>>();
    router_kernel<<<T_TOK, 256>>>(x, rw, rb);
    prefix_kernel<<<1, 32>>>(out, out_size);
    scatter_kernel<<<(T_TOK + 255) / 256, 256>>>();
    cvt_x_kernel<<<(T_TOK * DIM / 4 + 255) / 256, 256>>>(x);

    // join: GEMM1 needs both chains
    cudaStreamWaitEvent(0, g_ev_join, 0);

    moe_mma_kernel<DIM, true><<<dim3(FDIM / TN, T_TOK / TM, NE), 256, SMEM_SZ>>>(b1, nullptr);
    moe_mma_kernel<FDIM, false><<<dim3(DIM / TN, T_TOK / TM, NE), 256, SMEM_SZ>>>(b2, out);
}

// round 15
// speedup vs baseline: 1.1627x; 1.1068x over previous
#include <cuda_runtime.h>
#include <cuda_fp16.h>
#include <cstdint>

#define T_TOK 16384
#define DIM   1024
#define NE    8
#define FDIM  4096

#define TM 128
#define TN 128
#define TK 64
#define LDA 72          // padded fp16 K-stride in smem (conflict-free ldmatrix)
#define MAT_BYTES (128 * LDA * 2)      // 18432
#define STAGE_BYTES (2 * MAT_BYTES)    // Ah, Bh = 36864
#define NSTAGE 3
#define SMEM_SZ (NSTAGE * STAGE_BYTES) // 110592 -> 2 CTAs/SM

// ---------------- device scratch (referenced ONLY from device code) ----------------
__device__ int   g_idx[T_TOK];
__device__ int   g_counts[NE];
__device__ int   g_offsets[NE + 1];
__device__ int   g_cursor[NE];
__device__ int   g_perm[T_TOK];

__device__ __half g_xs[(size_t)T_TOK * DIM];        // gathered x, fp16
__device__ __half g_w1_h[(size_t)NE * FDIM * DIM];  // [e][n=F][k=D]
__device__ __half g_w2_h[(size_t)NE * DIM * FDIM];  // [e][n=D][k=F]
__device__ __half g_h[(size_t)T_TOK * FDIM];        // hidden, fp16

// ---------------- helpers ----------------
__device__ __forceinline__ uint32_t smem_u32(const void* p) {
    uint32_t a;
    asm("{ .reg .u64 t; cvta.to.shared.u64 t, %1; cvt.u32.u64 %0, t; }"
        : "=r"(a) : "l"(p));
    return a;
}

__device__ __forceinline__ void ldm_x4(uint32_t* r, uint32_t addr) {
    asm volatile("ldmatrix.sync.aligned.m8n8.x4.shared.b16 {%0,%1,%2,%3}, [%4];"
                 : "=r"(r[0]), "=r"(r[1]), "=r"(r[2]), "=r"(r[3]) : "r"(addr));
}
__device__ __forceinline__ void mma_f16_2(float* c, const uint32_t* a,
                                          uint32_t b0, uint32_t b1) {
    asm volatile(
        "mma.sync.aligned.m16n8k16.row.col.f32.f16.f16.f32 "
        "{%0,%1,%2,%3}, {%4,%5,%6,%7}, {%8,%9}, {%0,%1,%2,%3};"
        : "+f"(c[0]), "+f"(c[1]), "+f"(c[2]), "+f"(c[3])
        : "r"(a[0]), "r"(a[1]), "r"(a[2]), "r"(a[3]), "r"(b0), "r"(b1));
}
__device__ __forceinline__ void cp16(uint32_t sa, const void* g) {
    uint64_t ga = __cvta_generic_to_global(g);
    asm volatile("cp.async.cg.shared.global [%0], [%1], 16;" :: "r"(sa), "l"(ga));
}

// ---------------- router / prefix / scatter ----------------
__global__ void init_kernel() {
    int t = threadIdx.x;
    if (t < NE) { g_counts[t] = 0; g_cursor[t] = 0; }
}

// warp-per-token router; router_w staged in smem [DIM][9] (pad -> conflict-free).
__global__ __launch_bounds__(256) void router_kernel(
    const float* __restrict__ x, const float* __restrict__ rw,
    const float* __restrict__ rb)
{
    __shared__ float rws[DIM * 9];   // 36 KB
    int tid = threadIdx.x;
    for (int i = tid; i < DIM * NE; i += 256) {
        int d = i >> 3, e = i & 7;
        rws[d * 9 + e] = rw[i];
    }
    __syncthreads();

    int w = tid >> 5, lane = tid & 31;
    int t = blockIdx.x * 8 + w;
    const float* xr = x + (size_t)t * DIM;

    float s[NE];
    #pragma unroll
    for (int e = 0; e < NE; e++) s[e] = 0.f;

    for (int d = lane; d < DIM; d += 32) {
        float xv = xr[d];
        const float* r = &rws[d * 9];
        #pragma unroll
        for (int e = 0; e < NE; e++) s[e] += xv * r[e];
    }
    #pragma unroll
    for (int e = 0; e < NE; e++)
        #pragma unroll
        for (int o = 16; o; o >>= 1)
            s[e] += __shfl_down_sync(0xffffffffu, s[e], o);

    if (lane == 0) {
        int best = 0; float bv = s[0] + rb[0];
        #pragma unroll
        for (int e = 1; e < NE; e++) {
            float v = s[e] + rb[e];
            if (v > bv) { bv = v; best = e; }
        }
        g_idx[t] = best;
        atomicAdd(&g_counts[best], 1);
    }
}

__global__ void prefix_kernel(float* __restrict__ out, int out_size) {
    if (threadIdx.x == 0) {
        int acc = 0; float lb = 0.f;
        for (int e = 0; e < NE; e++) {
            g_offsets[e] = acc;
            acc += g_counts[e];
            float u = (float)g_counts[e] / (float)T_TOK - 1.0f / (float)NE;
            lb += u * u;
        }
        g_offsets[NE] = acc;
        lb /= (float)NE;
        if (out_size > T_TOK * DIM)
            out[(size_t)T_TOK * DIM] = lb;
    }
}

__global__ void scatter_kernel() {
    int t = blockIdx.x * blockDim.x + threadIdx.x;
    if (t < T_TOK) {
        int e = g_idx[t];
        int p = atomicAdd(&g_cursor[e], 1);
        g_perm[g_offsets[e] + p] = t;
    }
}

// ---------------- conversions ----------------
__global__ void cvt_x_kernel(const float* __restrict__ x) {
    size_t i = ((size_t)blockIdx.x * blockDim.x + threadIdx.x) * 4;
    if (i >= (size_t)T_TOK * DIM) return;
    int r = (int)(i / DIM), d = (int)(i % DIM);
    const float4 v = *(const float4*)(x + (size_t)g_perm[r] * DIM + d);
    __half2 t0; t0.x = __float2half(v.x); t0.y = __float2half(v.y);
    __half2 t1; t1.x = __float2half(v.z); t1.y = __float2half(v.w);
    *(__half2*)(g_xs + i)     = t0;
    *(__half2*)(g_xs + i + 2) = t1;
}

// transpose + round to fp16: src [SR, SC] per expert -> dst [SC, SR]
// 32(c) x 64(r) tiles; half2 coalesced stores.
template<int SR, int SC, bool W1>
__global__ __launch_bounds__(256) void tsplit_kernel(const float* __restrict__ w)
{
    __shared__ float tile[32][65];   // [c][r], pad -> conflict-free
    int e = blockIdx.z;
    int c0 = blockIdx.x * 32;
    int r0 = blockIdx.y * 64;
    const float* src = w + (size_t)e * SR * SC;
    int tx = threadIdx.x, ty = threadIdx.y;   // (32, 8)
    #pragma unroll
    for (int j = 0; j < 64; j += 8)
        tile[tx][ty + j] = src[(size_t)(r0 + ty + j) * SC + (c0 + tx)];
    __syncthreads();
    __half* oh = (W1 ? g_w1_h : g_w2_h) + (size_t)e * SR * SC;
    #pragma unroll
    for (int j = 0; j < 32; j += 8) {
        int c = ty + j;
        __half2 v;
        v.x = __float2half(tile[c][2 * tx]);
        v.y = __float2half(tile[c][2 * tx + 1]);
        *(__half2*)(oh + (size_t)(c0 + c) * SR + r0 + 2 * tx) = v;
    }
}

// ---------------- grouped fp16 mma.sync GEMM (single-pass) ----------------
// CTA 128x128, warp 64x32 (8 warps 2x4), TK=64. C = A[128,K] * B[128,K]^T
template<int KTOT, bool G1>
__global__ __launch_bounds__(256, 2) void moe_mma_kernel(
    const float* __restrict__ bias, float* __restrict__ Of)
{
    constexpr int NTOT = G1 ? FDIM : DIM;
    constexpr int NCH  = KTOT / TK;

    const __half* __restrict__ Ah = G1 ? g_xs : g_h;
    const __half* __restrict__ Bh = G1 ? g_w1_h : g_w2_h;

    int e = blockIdx.z;
    int seg0 = g_offsets[e], seg1 = g_offsets[e + 1];
    int m0 = seg0 + blockIdx.y * TM;
    if (m0 >= seg1) return;
    int mcnt = min(TM, seg1 - m0);
    int n0 = blockIdx.x * TN;

    extern __shared__ char smem[];
    uint32_t sbase = smem_u32(smem);

    int tid = threadIdx.x;
    int wid = tid >> 5, lane = tid & 31;
    int warp_m = (wid >> 2) * 64;   // 0 or 64
    int warp_n = (wid & 3) * 32;    // 0,32,64,96

    const __half* Beh = Bh + (size_t)e * NTOT * KTOT;
    const float* be = bias + (size_t)e * NTOT;

    auto prefetch = [&](int it) {
        if (it < NCH) {
            int k0 = it * TK;
            uint32_t stg = sbase + (uint32_t)(it % NSTAGE) * STAGE_BYTES;
            #pragma unroll
            for (int i = 0; i < 8; i++) {
                int c   = i * 256 + tid;          // 0..2047
                int mat = c >> 10;                // 0:Ah 1:Bh
                int rw  = (c & 1023) >> 3;        // 0..127
                int sg  = c & 7;                  // 16B segment in 128B row
                uint32_t sa = stg + mat * MAT_BYTES + (rw * LDA + sg * 8) * 2;
                const __half* gp;
                if (mat == 0) {
                    int gr = m0 + rw;
                    if (gr > T_TOK - 1) gr = T_TOK - 1;   // clamp; never stored
                    gp = Ah + (size_t)gr * KTOT + k0 + sg * 8;
                } else {
                    gp = Beh + (size_t)(n0 + rw) * KTOT + k0 + sg * 8;
                }
                cp16(sa, gp);
            }
        }
        asm volatile("cp.async.commit_group;" ::: "memory");
    };

    float acc[4][4][4];
    #pragma unroll
    for (int i = 0; i < 4; i++)
        #pragma unroll
        for (int j = 0; j < 4; j++)
            #pragma unroll
            for (int q = 0; q < 4; q++) acc[i][j][q] = 0.f;

    prefetch(0);
    prefetch(1);

    // B x4 address precompute: group g = lane>>3, lr = lane&7
    // row = warp_n + pair*16 + (g>>1)*8 + lr ; col = kst*16 + (g&1)*8
    int bg   = lane >> 3;
    int brow = ((bg >> 1) << 3) + (lane & 7);
    int bcolo = (bg & 1) << 3;

    for (int it = 0; it < NCH; ++it) {
        asm volatile("cp.async.wait_group 1;" ::: "memory");
        __syncthreads();        // stage `it` visible; stage (it-1) reads all done

        uint32_t stg = sbase + (uint32_t)(it % NSTAGE) * STAGE_BYTES;
        uint32_t sAh = stg;
        uint32_t sBh = stg + MAT_BYTES;

        #pragma unroll
        for (int kst = 0; kst < 4; ++kst) {
            uint32_t afh[4][4], bfh[2][4];
            int acol = kst * 16 + ((lane >> 4) << 3);
            int arow_off = (lane & 15);
            #pragma unroll
            for (int mt = 0; mt < 4; ++mt) {
                int row = warp_m + mt * 16 + arow_off;
                ldm_x4(afh[mt], sAh + (uint32_t)(row * LDA + acol) * 2);
            }
            int bcol = kst * 16 + bcolo;
            #pragma unroll
            for (int p = 0; p < 2; ++p) {
                int row = warp_n + p * 16 + brow;
                ldm_x4(bfh[p], sBh + (uint32_t)(row * LDA + bcol) * 2);
            }
            if (kst == 0)
                prefetch(it + 2);   // after critical ldmatrix issues; overwrites (it-1)%3
            // frag(nt=2p)   = {bfh[p][0], bfh[p][1]}  (n rows p*16+0..7)
            // frag(nt=2p+1) = {bfh[p][2], bfh[p][3]}  (n rows p*16+8..15)
            #pragma unroll
            for (int mt = 0; mt < 4; ++mt)
                #pragma unroll
                for (int p = 0; p < 2; ++p) {
                    mma_f16_2(acc[mt][2 * p],     afh[mt], bfh[p][0], bfh[p][1]);
                    mma_f16_2(acc[mt][2 * p + 1], afh[mt], bfh[p][2], bfh[p][3]);
                }
        }
    }

    // ---- epilogue ----
    int rbase = warp_m + (lane >> 2);
    int cbase = n0 + warp_n + (lane & 3) * 2;
    #pragma unroll
    for (int nt = 0; nt < 4; ++nt) {
        int gc = cbase + nt * 8;
        float b0 = be[gc], b1 = be[gc + 1];
        #pragma unroll
        for (int mt = 0; mt < 4; ++mt) {
            #pragma unroll
            for (int s = 0; s < 2; ++s) {
                int lr = rbase + mt * 16 + s * 8;
                if (lr < mcnt) {
                    int gr = m0 + lr;
                    float f0 = acc[mt][nt][2 * s]     + b0;
                    float f1 = acc[mt][nt][2 * s + 1] + b1;
                    if constexpr (G1) {
                        f0 = fmaxf(f0, 0.f);
                        f1 = fmaxf(f1, 0.f);
                        __half2 th;
                        th.x = __float2half(f0);
                        th.y = __float2half(f1);
                        *(__half2*)(g_h + (size_t)gr * FDIM + gc) = th;
                    } else {
                        int orow = g_perm[gr];
                        float2 v; v.x = f0; v.y = f1;
                        *(float2*)(Of + (size_t)orow * DIM + gc) = v;
                    }
                }
            }
        }
    }
}

// ---------------- static side-stream resources (host-side; no device memory) ----
static cudaStream_t g_side_stream;
static cudaEvent_t  g_ev_fork, g_ev_join;
static struct SideInit {
    SideInit() {
        cudaStreamCreateWithFlags(&g_side_stream, cudaStreamNonBlocking);
        cudaEventCreateWithFlags(&g_ev_fork, cudaEventDisableTiming);
        cudaEventCreateWithFlags(&g_ev_join, cudaEventDisableTiming);
    }
} g_side_init;

// ---------------- launch ----------------
extern "C" void kernel_launch(void* const* d_in, const int* in_sizes, int n_in,
                              void* d_out, int out_size)
{
    const float* x  = (const float*)d_in[0];
    const float* rw = (const float*)d_in[1];
    const float* rb = (const float*)d_in[2];
    const float* w1 = (const float*)d_in[3];
    const float* b1 = (const float*)d_in[4];
    const float* w2 = (const float*)d_in[5];
    const float* b2 = (const float*)d_in[6];
    float* out = (float*)d_out;

    cudaFuncSetAttribute(moe_mma_kernel<DIM, true>,
                         cudaFuncAttributeMaxDynamicSharedMemorySize, SMEM_SZ);
    cudaFuncSetAttribute(moe_mma_kernel<FDIM, false>,
                         cudaFuncAttributeMaxDynamicSharedMemorySize, SMEM_SZ);

    // fork: tsplit (depends only on w1/w2) runs on side stream concurrently
    // with the router -> prefix -> scatter -> cvt_x chain on the main stream.
    cudaEventRecord(g_ev_fork, 0);
    cudaStreamWaitEvent(g_side_stream, g_ev_fork, 0);

    tsplit_kernel<DIM, FDIM, true>
        <<<dim3(FDIM / 32, DIM / 64, NE), dim3(32, 8), 0, g_side_stream>>>(w1);
    tsplit_kernel<FDIM, DIM, false>
        <<<dim3(DIM / 32, FDIM / 64, NE), dim3(32, 8), 0, g_side_stream>>>(w2);
    cudaEventRecord(g_ev_join, g_side_stream);

    init_kernel<<<1, 32>>>();
    router_kernel<<<T_TOK / 8, 256>>>(x, rw, rb);
    prefix_kernel<<<1, 32>>>(out, out_size);
    scatter_kernel<<<(T_TOK + 255) / 256, 256>>>();
    cvt_x_kernel<<<(T_TOK * DIM / 4 + 255) / 256, 256>>>(x);

    // join: GEMM1 needs both chains
    cudaStreamWaitEvent(0, g_ev_join, 0);

    moe_mma_kernel<DIM, true><<<dim3(FDIM / TN, T_TOK / TM, NE), 256, SMEM_SZ>>>(b1, nullptr);
    moe_mma_kernel<FDIM, false><<<dim3(DIM / TN, T_TOK / TM, NE), 256, SMEM_SZ>>>(b2, out);
}

// round 16
// speedup vs baseline: 1.2008x; 1.0327x over previous
#include <cuda_runtime.h>
#include <cuda_fp16.h>
#include <cstdint>

#define T_TOK 16384
#define DIM   1024
#define NE    8
#define FDIM  4096

#define TM 128
#define TN 128
#define TK 64
#define LDA 72          // padded fp16 K-stride in smem (conflict-free ldmatrix)
#define MAT_BYTES (128 * LDA * 2)      // 18432
#define STAGE_BYTES (2 * MAT_BYTES)    // Ah, Bh = 36864
#define NSTAGE 3
#define SMEM_SZ (NSTAGE * STAGE_BYTES) // 110592 -> 2 CTAs/SM

// ---------------- device scratch (referenced ONLY from device code) ----------------
__device__ int   g_idx[T_TOK];
__device__ int   g_counts[NE];
__device__ int   g_offsets[NE + 1];
__device__ int   g_cursor[NE];
__device__ int   g_perm[T_TOK];

__device__ __half g_xs[(size_t)T_TOK * DIM];        // x in fp16, TOKEN order
__device__ __half g_w1_h[(size_t)NE * FDIM * DIM];  // [e][n=F][k=D]
__device__ __half g_w2_h[(size_t)NE * DIM * FDIM];  // [e][n=D][k=F]
__device__ __half g_h[(size_t)T_TOK * FDIM];        // hidden, perm order

// ---------------- helpers ----------------
__device__ __forceinline__ uint32_t smem_u32(const void* p) {
    uint32_t a;
    asm("{ .reg .u64 t; cvta.to.shared.u64 t, %1; cvt.u32.u64 %0, t; }"
        : "=r"(a) : "l"(p));
    return a;
}

__device__ __forceinline__ void ldm_x4(uint32_t* r, uint32_t addr) {
    asm volatile("ldmatrix.sync.aligned.m8n8.x4.shared.b16 {%0,%1,%2,%3}, [%4];"
                 : "=r"(r[0]), "=r"(r[1]), "=r"(r[2]), "=r"(r[3]) : "r"(addr));
}
__device__ __forceinline__ void mma_f16_2(float* c, const uint32_t* a,
                                          uint32_t b0, uint32_t b1) {
    asm volatile(
        "mma.sync.aligned.m16n8k16.row.col.f32.f16.f16.f32 "
        "{%0,%1,%2,%3}, {%4,%5,%6,%7}, {%8,%9}, {%0,%1,%2,%3};"
        : "+f"(c[0]), "+f"(c[1]), "+f"(c[2]), "+f"(c[3])
        : "r"(a[0]), "r"(a[1]), "r"(a[2]), "r"(a[3]), "r"(b0), "r"(b1));
}
__device__ __forceinline__ void cp16(uint32_t sa, const void* g) {
    uint64_t ga = __cvta_generic_to_global(g);
    asm volatile("cp.async.cg.shared.global [%0], [%1], 16;" :: "r"(sa), "l"(ga));
}

// ---------------- router / prefix / scatter ----------------
__global__ void init_kernel() {
    int t = threadIdx.x;
    if (t < NE) { g_counts[t] = 0; g_cursor[t] = 0; }
}

// warp-per-token router with fused fp16 conversion (token-order store).
__global__ __launch_bounds__(256) void router_kernel(
    const float* __restrict__ x, const float* __restrict__ rw,
    const float* __restrict__ rb)
{
    __shared__ float rws[DIM * 9];   // 36 KB, pad -> conflict-free
    int tid = threadIdx.x;
    for (int i = tid; i < DIM * NE; i += 256) {
        int d = i >> 3, e = i & 7;
        rws[d * 9 + e] = rw[i];
    }
    __syncthreads();

    int w = tid >> 5, lane = tid & 31;
    int t = blockIdx.x * 8 + w;
    const float* xr = x + (size_t)t * DIM;
    __half* xo = g_xs + (size_t)t * DIM;

    float s[NE];
    #pragma unroll
    for (int e = 0; e < NE; e++) s[e] = 0.f;

    for (int d = lane; d < DIM; d += 32) {
        float xv = xr[d];
        xo[d] = __float2half(xv);            // fused fp16 conversion
        const float* r = &rws[d * 9];
        #pragma unroll
        for (int e = 0; e < NE; e++) s[e] += xv * r[e];
    }
    #pragma unroll
    for (int e = 0; e < NE; e++)
        #pragma unroll
        for (int o = 16; o; o >>= 1)
            s[e] += __shfl_down_sync(0xffffffffu, s[e], o);

    if (lane == 0) {
        int best = 0; float bv = s[0] + rb[0];
        #pragma unroll
        for (int e = 1; e < NE; e++) {
            float v = s[e] + rb[e];
            if (v > bv) { bv = v; best = e; }
        }
        g_idx[t] = best;
        atomicAdd(&g_counts[best], 1);
    }
}

__global__ void prefix_kernel(float* __restrict__ out, int out_size) {
    if (threadIdx.x == 0) {
        int acc = 0; float lb = 0.f;
        for (int e = 0; e < NE; e++) {
            g_offsets[e] = acc;
            acc += g_counts[e];
            float u = (float)g_counts[e] / (float)T_TOK - 1.0f / (float)NE;
            lb += u * u;
        }
        g_offsets[NE] = acc;
        lb /= (float)NE;
        if (out_size > T_TOK * DIM)
            out[(size_t)T_TOK * DIM] = lb;
    }
}

__global__ void scatter_kernel() {
    int t = blockIdx.x * blockDim.x + threadIdx.x;
    if (t < T_TOK) {
        int e = g_idx[t];
        int p = atomicAdd(&g_cursor[e], 1);
        g_perm[g_offsets[e] + p] = t;
    }
}

// ---------------- weight transpose + fp16 ----------------
// src [SR, SC] per expert -> dst [SC, SR]; 32(c) x 64(r) tiles; half2 stores.
template<int SR, int SC, bool W1>
__global__ __launch_bounds__(256) void tsplit_kernel(const float* __restrict__ w)
{
    __shared__ float tile[32][65];   // [c][r], pad -> conflict-free
    int e = blockIdx.z;
    int c0 = blockIdx.x * 32;
    int r0 = blockIdx.y * 64;
    const float* src = w + (size_t)e * SR * SC;
    int tx = threadIdx.x, ty = threadIdx.y;   // (32, 8)
    #pragma unroll
    for (int j = 0; j < 64; j += 8)
        tile[tx][ty + j] = src[(size_t)(r0 + ty + j) * SC + (c0 + tx)];
    __syncthreads();
    __half* oh = (W1 ? g_w1_h : g_w2_h) + (size_t)e * SR * SC;
    #pragma unroll
    for (int j = 0; j < 32; j += 8) {
        int c = ty + j;
        __half2 v;
        v.x = __float2half(tile[c][2 * tx]);
        v.y = __float2half(tile[c][2 * tx + 1]);
        *(__half2*)(oh + (size_t)(c0 + c) * SR + r0 + 2 * tx) = v;
    }
}

// ---------------- grouped fp16 mma.sync GEMM (single-pass) ----------------
// CTA 128x128, warp 64x32 (8 warps 2x4), TK=64. C = A[128,K] * B[128,K]^T
// G1: A rows gathered from token-order g_xs via g_perm (precomputed pointers).
template<int KTOT, bool G1>
__global__ __launch_bounds__(256, 2) void moe_mma_kernel(
    const float* __restrict__ bias, float* __restrict__ Of)
{
    constexpr int NTOT = G1 ? FDIM : DIM;
    constexpr int NCH  = KTOT / TK;

    const __half* __restrict__ Bh = G1 ? g_w1_h : g_w2_h;

    int e = blockIdx.z;
    int seg0 = g_offsets[e], seg1 = g_offsets[e + 1];
    int m0 = seg0 + blockIdx.y * TM;
    if (m0 >= seg1) return;
    int mcnt = min(TM, seg1 - m0);
    int n0 = blockIdx.x * TN;

    extern __shared__ char smem[];
    uint32_t sbase = smem_u32(smem);

    int tid = threadIdx.x;
    int wid = tid >> 5, lane = tid & 31;
    int warp_m = (wid >> 2) * 64;   // 0 or 64
    int warp_n = (wid & 3) * 32;    // 0,32,64,96

    const __half* Beh = Bh + (size_t)e * NTOT * KTOT;
    const float* be = bias + (size_t)e * NTOT;

    // A-row gather pointers: thread owns 4 fixed A rows (rw = i*32 + tid/8)
    const __half* arowp[4];
    int asg = tid & 7;               // 16B segment within 128B row
    #pragma unroll
    for (int i = 0; i < 4; i++) {
        int gr = m0 + i * 32 + (tid >> 3);
        if (gr > T_TOK - 1) gr = T_TOK - 1;     // clamp; never stored
        if (G1) gr = g_perm[gr];                // permuted pos -> token
        arowp[i] = (G1 ? g_xs : g_h) + (size_t)gr * KTOT + asg * 8;
    }

    auto prefetch = [&](int it) {
        if (it < NCH) {
            int k0 = it * TK;
            uint32_t stg = sbase + (uint32_t)(it % NSTAGE) * STAGE_BYTES;
            uint32_t sa0 = stg + ((tid >> 3) * LDA + asg * 8) * 2;
            #pragma unroll
            for (int i = 0; i < 4; i++)          // A rows
                cp16(sa0 + (uint32_t)i * 32 * LDA * 2, arowp[i] + k0);
            #pragma unroll
            for (int i = 0; i < 4; i++) {        // B rows
                int rw = i * 32 + (tid >> 3);
                cp16(stg + MAT_BYTES + (rw * LDA + asg * 8) * 2,
                     Beh + (size_t)(n0 + rw) * KTOT + k0 + asg * 8);
            }
        }
        asm volatile("cp.async.commit_group;" ::: "memory");
    };

    float acc[4][4][4];
    #pragma unroll
    for (int i = 0; i < 4; i++)
        #pragma unroll
        for (int j = 0; j < 4; j++)
            #pragma unroll
            for (int q = 0; q < 4; q++) acc[i][j][q] = 0.f;

    prefetch(0);
    prefetch(1);

    // B x4 address precompute: group g = lane>>3, lr = lane&7
    int bg   = lane >> 3;
    int brow = ((bg >> 1) << 3) + (lane & 7);
    int bcolo = (bg & 1) << 3;

    for (int it = 0; it < NCH; ++it) {
        asm volatile("cp.async.wait_group 1;" ::: "memory");
        __syncthreads();        // stage `it` visible; stage (it-1) reads all done

        uint32_t stg = sbase + (uint32_t)(it % NSTAGE) * STAGE_BYTES;
        uint32_t sAh = stg;
        uint32_t sBh = stg + MAT_BYTES;

        #pragma unroll
        for (int kst = 0; kst < 4; ++kst) {
            uint32_t afh[4][4], bfh[2][4];
            int acol = kst * 16 + ((lane >> 4) << 3);
            int arow_off = (lane & 15);
            #pragma unroll
            for (int mt = 0; mt < 4; ++mt) {
                int row = warp_m + mt * 16 + arow_off;
                ldm_x4(afh[mt], sAh + (uint32_t)(row * LDA + acol) * 2);
            }
            int bcol = kst * 16 + bcolo;
            #pragma unroll
            for (int p = 0; p < 2; ++p) {
                int row = warp_n + p * 16 + brow;
                ldm_x4(bfh[p], sBh + (uint32_t)(row * LDA + bcol) * 2);
            }
            if (kst == 0)
                prefetch(it + 2);   // after critical ldmatrix issues; overwrites (it-1)%3
            #pragma unroll
            for (int mt = 0; mt < 4; ++mt)
                #pragma unroll
                for (int p = 0; p < 2; ++p) {
                    mma_f16_2(acc[mt][2 * p],     afh[mt], bfh[p][0], bfh[p][1]);
                    mma_f16_2(acc[mt][2 * p + 1], afh[mt], bfh[p][2], bfh[p][3]);
                }
        }
    }

    // ---- epilogue ----
    int rbase = warp_m + (lane >> 2);
    int cbase = n0 + warp_n + (lane & 3) * 2;
    #pragma unroll
    for (int nt = 0; nt < 4; ++nt) {
        int gc = cbase + nt * 8;
        float b0 = be[gc], b1 = be[gc + 1];
        #pragma unroll
        for (int mt = 0; mt < 4; ++mt) {
            #pragma unroll
            for (int s = 0; s < 2; ++s) {
                int lr = rbase + mt * 16 + s * 8;
                if (lr < mcnt) {
                    int gr = m0 + lr;
                    float f0 = acc[mt][nt][2 * s]     + b0;
                    float f1 = acc[mt][nt][2 * s + 1] + b1;
                    if constexpr (G1) {
                        f0 = fmaxf(f0, 0.f);
                        f1 = fmaxf(f1, 0.f);
                        __half2 th;
                        th.x = __float2half(f0);
                        th.y = __float2half(f1);
                        *(__half2*)(g_h + (size_t)gr * FDIM + gc) = th;
                    } else {
                        int orow = g_perm[gr];
                        float2 v; v.x = f0; v.y = f1;
                        *(float2*)(Of + (size_t)orow * DIM + gc) = v;
                    }
                }
            }
        }
    }
}

// ---------------- static side-stream resources (host-side; no device memory) ----
static cudaStream_t g_side_stream;
static cudaEvent_t  g_ev_fork, g_ev_join;
static struct SideInit {
    SideInit() {
        cudaStreamCreateWithFlags(&g_side_stream, cudaStreamNonBlocking);
        cudaEventCreateWithFlags(&g_ev_fork, cudaEventDisableTiming);
        cudaEventCreateWithFlags(&g_ev_join, cudaEventDisableTiming);
    }
} g_side_init;

// ---------------- launch ----------------
extern "C" void kernel_launch(void* const* d_in, const int* in_sizes, int n_in,
                              void* d_out, int out_size)
{
    const float* x  = (const float*)d_in[0];
    const float* rw = (const float*)d_in[1];
    const float* rb = (const float*)d_in[2];
    const float* w1 = (const float*)d_in[3];
    const float* b1 = (const float*)d_in[4];
    const float* w2 = (const float*)d_in[5];
    const float* b2 = (const float*)d_in[6];
    float* out = (float*)d_out;

    cudaFuncSetAttribute(moe_mma_kernel<DIM, true>,
                         cudaFuncAttributeMaxDynamicSharedMemorySize, SMEM_SZ);
    cudaFuncSetAttribute(moe_mma_kernel<FDIM, false>,
                         cudaFuncAttributeMaxDynamicSharedMemorySize, SMEM_SZ);

    // fork: tsplit (depends only on w1/w2) runs on the side stream concurrently
    // with the router(+cvt) -> prefix -> scatter chain on the main stream.
    cudaEventRecord(g_ev_fork, 0);
    cudaStreamWaitEvent(g_side_stream, g_ev_fork, 0);

    tsplit_kernel<DIM, FDIM, true>
        <<<dim3(FDIM / 32, DIM / 64, NE), dim3(32, 8), 0, g_side_stream>>>(w1);
    tsplit_kernel<FDIM, DIM, false>
        <<<dim3(DIM / 32, FDIM / 64, NE), dim3(32, 8), 0, g_side_stream>>>(w2);
    cudaEventRecord(g_ev_join, g_side_stream);

    init_kernel<<<1, 32>>>();
    router_kernel<<<T_TOK / 8, 256>>>(x, rw, rb);
    prefix_kernel<<<1, 32>>>(out, out_size);
    scatter_kernel<<<(T_TOK + 255) / 256, 256>>>();

    // join: GEMM1 needs both chains
    cudaStreamWaitEvent(0, g_ev_join, 0);

    moe_mma_kernel<DIM, true><<<dim3(FDIM / TN, T_TOK / TM, NE), 256, SMEM_SZ>>>(b1, nullptr);
    moe_mma_kernel<FDIM, false><<<dim3(DIM / TN, T_TOK / TM, NE), 256, SMEM_SZ>>>(b2, out);
}